// round 4
// baseline (speedup 1.0000x reference)
#include <cuda_runtime.h>
#include <float.h>

// Per-channel min/max over [C, N] fp32 (C=1024, N=32768).
// Each channel is split across SPLIT CTAs (32KB chunks) for even SM load
// balance; the last CTA to finish a channel combines the partials
// (threadFenceReduction pattern) — single kernel, no extra launches.

#define SPLIT 4
#define MAXC 8192

__device__ float        g_pmin[MAXC * SPLIT];
__device__ float        g_pmax[MAXC * SPLIT];
__device__ unsigned int g_count[MAXC];   // zero-init at load; reset by finisher

__global__ void __launch_bounds__(256)
minmax_split_kernel(const float4* __restrict__ in, float* __restrict__ out,
                    int C, int N4) {
    const int b    = blockIdx.x;
    const int c    = b >> 2;        // channel
    const int part = b & (SPLIT - 1);

    const int chunk = (N4 + SPLIT - 1) / SPLIT;
    const int start = part * chunk;
    const int end   = min(start + chunk, N4);

    const float4* p = in + (size_t)c * N4;

    float mn = FLT_MAX;
    float mx = -FLT_MAX;

    // 2048 float4 per CTA / 256 threads = 8 iterations. Unroll fully to
    // front-batch LDG.128s (high MLP). __ldcs: evict-first streaming.
    #pragma unroll 8
    for (int i = start + threadIdx.x; i < end; i += 256) {
        float4 v = __ldcs(p + i);
        mn = fminf(mn, fminf(fminf(v.x, v.y), fminf(v.z, v.w)));
        mx = fmaxf(mx, fmaxf(fmaxf(v.x, v.y), fmaxf(v.z, v.w)));
    }

    // Warp butterfly
    #pragma unroll
    for (int o = 16; o > 0; o >>= 1) {
        mn = fminf(mn, __shfl_xor_sync(0xffffffffu, mn, o));
        mx = fmaxf(mx, __shfl_xor_sync(0xffffffffu, mx, o));
    }

    __shared__ float smn[8], smx[8];
    const int wid = threadIdx.x >> 5;
    const int lid = threadIdx.x & 31;
    if (lid == 0) { smn[wid] = mn; smx[wid] = mx; }
    __syncthreads();

    if (threadIdx.x == 0) {
        #pragma unroll
        for (int w = 1; w < 8; ++w) {
            mn = fminf(mn, smn[w]);
            mx = fmaxf(mx, smx[w]);
        }
        // Publish partial
        g_pmin[b] = mn;
        g_pmax[b] = mx;
        __threadfence();
        unsigned int old = atomicAdd(&g_count[c], 1u);
        if (old == SPLIT - 1) {
            __threadfence();  // acquire: make peers' partials visible
            float fmn = FLT_MAX, fmx = -FLT_MAX;
            #pragma unroll
            for (int k = 0; k < SPLIT; ++k) {
                fmn = fminf(fmn, g_pmin[c * SPLIT + k]);
                fmx = fmaxf(fmx, g_pmax[c * SPLIT + k]);
            }
            out[c]     = fmn;
            out[C + c] = fmx;
            g_count[c] = 0;   // reset for next graph replay (deterministic)
        }
    }
}

// Fallback: one CTA per channel, scalar-safe (any N).
__global__ void __launch_bounds__(256)
minmax_simple_kernel(const float* __restrict__ in, float* __restrict__ out,
                     int C, int N) {
    const int c = blockIdx.x;
    const float* row = in + (size_t)c * N;
    float mn = FLT_MAX, mx = -FLT_MAX;
    for (int i = threadIdx.x; i < N; i += 256) {
        float v = row[i];
        mn = fminf(mn, v);
        mx = fmaxf(mx, v);
    }
    #pragma unroll
    for (int o = 16; o > 0; o >>= 1) {
        mn = fminf(mn, __shfl_xor_sync(0xffffffffu, mn, o));
        mx = fmaxf(mx, __shfl_xor_sync(0xffffffffu, mx, o));
    }
    __shared__ float smn[8], smx[8];
    const int wid = threadIdx.x >> 5, lid = threadIdx.x & 31;
    if (lid == 0) { smn[wid] = mn; smx[wid] = mx; }
    __syncthreads();
    if (threadIdx.x == 0) {
        #pragma unroll
        for (int w = 1; w < 8; ++w) {
            mn = fminf(mn, smn[w]);
            mx = fmaxf(mx, smx[w]);
        }
        out[c] = mn;
        out[C + c] = mx;
    }
}

extern "C" void kernel_launch(void* const* d_in, const int* in_sizes, int n_in,
                              void* d_out, int out_size) {
    const float* in = (const float*)d_in[0];
    float* out = (float*)d_out;

    const int C = out_size / 2;       // 1024
    const int N = in_sizes[0] / C;    // 32768

    if ((N & 3) == 0 && C <= MAXC) {
        const int N4 = N >> 2;
        minmax_split_kernel<<<C * SPLIT, 256>>>((const float4*)in, out, C, N4);
    } else {
        minmax_simple_kernel<<<C, 256>>>(in, out, C, N);
    }
}

// round 5
// speedup vs baseline: 1.0252x; 1.0252x over previous
#include <cuda_runtime.h>
#include <float.h>

// Per-channel min/max over [C, N] fp32 (C=1024, N=32768).
// One CTA per channel (1024 CTAs @ occ 8 = exactly one wave).
// Guard-free inner loop, two independent load streams per thread,
// dual accumulators, L2-only (__ldcg) streaming loads.

__global__ void __launch_bounds__(256, 8)
minmax_fast_kernel(const float4* __restrict__ in, float* __restrict__ out,
                   int C, int N4) {
    const int c = blockIdx.x;
    const float4* __restrict__ p = in + (size_t)c * N4;

    const int half  = N4 >> 1;          // 4096
    const int iters = half >> 8;        // half / 256 = 16 (exact, guard-free)

    const float4* __restrict__ p0 = p + threadIdx.x;
    const float4* __restrict__ p1 = p + half + threadIdx.x;

    float mn0 = FLT_MAX,  mn1 = FLT_MAX;
    float mx0 = -FLT_MAX, mx1 = -FLT_MAX;

    #pragma unroll 4
    for (int k = 0; k < iters; ++k) {
        float4 a = __ldcg(p0 + (size_t)k * 256);
        float4 b = __ldcg(p1 + (size_t)k * 256);
        mn0 = fminf(mn0, fminf(fminf(a.x, a.y), fminf(a.z, a.w)));
        mx0 = fmaxf(mx0, fmaxf(fmaxf(a.x, a.y), fmaxf(a.z, a.w)));
        mn1 = fminf(mn1, fminf(fminf(b.x, b.y), fminf(b.z, b.w)));
        mx1 = fmaxf(mx1, fmaxf(fmaxf(b.x, b.y), fmaxf(b.z, b.w)));
    }

    float mn = fminf(mn0, mn1);
    float mx = fmaxf(mx0, mx1);

    // Warp butterfly reduction
    #pragma unroll
    for (int o = 16; o > 0; o >>= 1) {
        mn = fminf(mn, __shfl_xor_sync(0xffffffffu, mn, o));
        mx = fmaxf(mx, __shfl_xor_sync(0xffffffffu, mx, o));
    }

    __shared__ float smn[8], smx[8];
    const int wid = threadIdx.x >> 5;
    const int lid = threadIdx.x & 31;
    if (lid == 0) { smn[wid] = mn; smx[wid] = mx; }
    __syncthreads();

    if (threadIdx.x == 0) {
        #pragma unroll
        for (int w = 1; w < 8; ++w) {
            mn = fminf(mn, smn[w]);
            mx = fmaxf(mx, smx[w]);
        }
        out[c]     = mn;   // min_vals
        out[C + c] = mx;   // max_vals
    }
}

// Fallback: one CTA per channel, scalar-safe (any N).
__global__ void __launch_bounds__(256)
minmax_simple_kernel(const float* __restrict__ in, float* __restrict__ out,
                     int C, int N) {
    const int c = blockIdx.x;
    const float* row = in + (size_t)c * N;
    float mn = FLT_MAX, mx = -FLT_MAX;
    for (int i = threadIdx.x; i < N; i += 256) {
        float v = row[i];
        mn = fminf(mn, v);
        mx = fmaxf(mx, v);
    }
    #pragma unroll
    for (int o = 16; o > 0; o >>= 1) {
        mn = fminf(mn, __shfl_xor_sync(0xffffffffu, mn, o));
        mx = fmaxf(mx, __shfl_xor_sync(0xffffffffu, mx, o));
    }
    __shared__ float smn[8], smx[8];
    const int wid = threadIdx.x >> 5, lid = threadIdx.x & 31;
    if (lid == 0) { smn[wid] = mn; smx[wid] = mx; }
    __syncthreads();
    if (threadIdx.x == 0) {
        #pragma unroll
        for (int w = 1; w < 8; ++w) {
            mn = fminf(mn, smn[w]);
            mx = fmaxf(mx, smx[w]);
        }
        out[c] = mn;
        out[C + c] = mx;
    }
}

extern "C" void kernel_launch(void* const* d_in, const int* in_sizes, int n_in,
                              void* d_out, int out_size) {
    const float* in = (const float*)d_in[0];
    float* out = (float*)d_out;

    const int C = out_size / 2;       // 1024
    const int N = in_sizes[0] / C;    // 32768

    // Fast path requires N divisible by 4 (float4) and N/4 divisible by 512
    // (two guard-free 256-stride streams).
    if ((N & 3) == 0 && ((N >> 2) & 511) == 0) {
        minmax_fast_kernel<<<C, 256>>>((const float4*)in, out, C, N >> 2);
    } else {
        minmax_simple_kernel<<<C, 256>>>(in, out, C, N);
    }
}